// round 1
// baseline (speedup 1.0000x reference)
#include <cuda_runtime.h>
#include <cuda_bf16.h>
#include <math.h>

#define NN 50000
#define EE 400000
#define ET 450000   // EE + NN self loops
#define EPSN 1e-5f

// ---------------- scratch (device globals; no allocation allowed) ------------
__device__ float g_A[(size_t)NN * 256];       // h1 -> h1n -> h2n
__device__ float g_B[(size_t)NN * 256];       // gat1 accum/centered -> [h2 | gat2 accum/centered]
__device__ float g_alpha[(size_t)ET * 4];     // exp(alpha) per edge/head (layer2 uses stride 2)
__device__ float g_den[(size_t)NN * 4];       // softmax denominators
__device__ float g_alS[(size_t)NN * 4];
__device__ float g_alD[(size_t)NN * 4];
__device__ float g_colstats[512];             // [0:256) colsum, [256:512) colsq
__device__ float g_eamsum[2];
__device__ float g_v1[8];                     // v1[h*2+f]
__device__ float g_v2[4];
__device__ float g_la1[4];                    // self-loop al_e, layer1
__device__ float g_la2[2];

// ---------------- utility ----------------------------------------------------
__global__ void k_zero(float* p, int n) {
    int i = blockIdx.x * blockDim.x + threadIdx.x;
    int st = gridDim.x * blockDim.x;
    for (; i < n; i += st) p[i] = 0.f;
}

// ---------------- edge_attr mean ---------------------------------------------
__global__ void k_eamean(const float* __restrict__ ea) {
    float s0 = 0.f, s1 = 0.f;
    for (int e = blockIdx.x * blockDim.x + threadIdx.x; e < EE; e += gridDim.x * blockDim.x) {
        s0 += ea[2 * e];
        s1 += ea[2 * e + 1];
    }
    for (int o = 16; o; o >>= 1) {
        s0 += __shfl_down_sync(0xFFFFFFFFu, s0, o);
        s1 += __shfl_down_sync(0xFFFFFFFFu, s1, o);
    }
    __shared__ float sh[16];
    int lane = threadIdx.x & 31, wid = threadIdx.x >> 5;
    if (lane == 0) { sh[wid] = s0; sh[8 + wid] = s1; }
    __syncthreads();
    if (threadIdx.x == 0) {
        float a = 0.f, b = 0.f;
        for (int w = 0; w < 8; w++) { a += sh[w]; b += sh[8 + w]; }
        atomicAdd(&g_eamsum[0], a);
        atomicAdd(&g_eamsum[1], b);
    }
}

// ---------------- precompute v vectors + self-loop al_e ----------------------
__global__ void k_prep(const float* __restrict__ We1, const float* __restrict__ ae1,
                       const float* __restrict__ We2, const float* __restrict__ ae2) {
    int t = threadIdx.x;
    if (t < 8) {                    // v1[h*2+f], h<4 f<2
        int h = t >> 1, f = t & 1;
        float s = 0.f;
        for (int d = 0; d < 64; d++) s += We1[f * 256 + h * 64 + d] * ae1[h * 64 + d];
        g_v1[t] = s;
    } else if (t < 12) {            // v2
        int tt = t - 8, h = tt >> 1, f = tt & 1;
        float s = 0.f;
        for (int d = 0; d < 64; d++) s += We2[f * 128 + h * 64 + d] * ae2[h * 64 + d];
        g_v2[tt] = s;
    }
    __syncthreads();
    if (t == 0) {
        float e0 = g_eamsum[0] / (float)EE;
        float e1 = g_eamsum[1] / (float)EE;
        for (int h = 0; h < 4; h++) g_la1[h] = e0 * g_v1[2 * h] + e1 * g_v1[2 * h + 1];
        for (int h = 0; h < 2; h++) g_la2[h] = e0 * g_v2[2 * h] + e1 * g_v2[2 * h + 1];
    }
}

// ---------------- layer1: h1 = x @ W1, plus per-node attention logits --------
__global__ void k_h1(const float* __restrict__ x, const float* __restrict__ W1,
                     const float* __restrict__ as1, const float* __restrict__ ad1) {
    int n = blockIdx.x;
    int j = threadIdx.x;
    __shared__ float w1s[768];
    w1s[j] = W1[j]; w1s[256 + j] = W1[256 + j]; w1s[512 + j] = W1[512 + j];
    __syncthreads();
    float x0 = __ldg(&x[3 * n]), x1 = __ldg(&x[3 * n + 1]), x2 = __ldg(&x[3 * n + 2]);
    float h = x0 * w1s[j] + x1 * w1s[256 + j] + x2 * w1s[512 + j];
    g_A[(size_t)n * 256 + j] = h;
    float vs = h * as1[j];
    float vd = h * ad1[j];
    for (int o = 16; o; o >>= 1) {
        vs += __shfl_down_sync(0xFFFFFFFFu, vs, o);
        vd += __shfl_down_sync(0xFFFFFFFFu, vd, o);
    }
    __shared__ float sS[8], sD[8];
    int lane = j & 31, wid = j >> 5;
    if (lane == 0) { sS[wid] = vs; sD[wid] = vd; }
    __syncthreads();
    if (j < 4) {
        g_alS[n * 4 + j] = sS[2 * j] + sS[2 * j + 1];
        g_alD[n * 4 + j] = sD[2 * j] + sD[2 * j + 1];
    }
}

// ---------------- alpha pass (exp + denominator), layer1 ---------------------
__global__ void k_alpha1(const int* __restrict__ ei, const float* __restrict__ ea) {
    int idx = blockIdx.x * blockDim.x + threadIdx.x;
    if (idx >= ET * 4) return;
    int e = idx >> 2, h = idx & 3;
    int s, d;
    float ale;
    if (e < EE) {
        s = ei[e]; d = ei[EE + e];
        float e0 = ea[2 * e], e1 = ea[2 * e + 1];
        ale = e0 * g_v1[2 * h] + e1 * g_v1[2 * h + 1];
    } else {
        s = e - EE; d = s; ale = g_la1[h];
    }
    float a = g_alS[s * 4 + h] + g_alD[d * 4 + h] + ale;
    a = a > 0.f ? a : 0.2f * a;
    float ex = __expf(a);
    g_alpha[idx] = ex;
    atomicAdd(&g_den[d * 4 + h], ex);
}

// ---------------- message scatter, layer1 (256 features) ---------------------
__global__ void k_msg1(const int* __restrict__ ei) {
    int e = blockIdx.x;
    int j = threadIdx.x;
    __shared__ float w[4];
    __shared__ int sh_s, sh_d;
    if (j == 0) {
        int s, d;
        if (e < EE) { s = ei[e]; d = ei[EE + e]; } else { s = e - EE; d = s; }
        sh_s = s; sh_d = d;
#pragma unroll
        for (int h = 0; h < 4; h++) w[h] = g_alpha[e * 4 + h] / g_den[d * 4 + h];
    }
    __syncthreads();
    atomicAdd(&g_B[(size_t)sh_d * 256 + j], g_A[(size_t)sh_s * 256 + j] * w[j >> 6]);
}

// ---------------- GraphNorm helpers ------------------------------------------
__global__ void k_colsum(const float* __restrict__ X, int C, int rpb) {
    int j = threadIdx.x;
    int r0 = blockIdx.x * rpb;
    int r1 = min(r0 + rpb, NN);
    float acc = 0.f;
    for (int r = r0; r < r1; r++) acc += X[(size_t)r * C + j];
    atomicAdd(&g_colstats[j], acc);
}

__global__ void k_center_var(float* X, const float* __restrict__ b,
                             const float* __restrict__ ms, int C, int rpb) {
    int j = threadIdx.x;
    int r0 = blockIdx.x * rpb;
    int r1 = min(r0 + rpb, NN);
    float bj = b[j];
    float mean = g_colstats[j] * (1.0f / NN) + bj;   // mean(gat + b)
    float sub = mean * ms[j];
    float acc = 0.f;
    for (int r = r0; r < r1; r++) {
        float t = X[(size_t)r * C + j] + bj - sub;
        X[(size_t)r * C + j] = t;
        acc += t * t;
    }
    atomicAdd(&g_colstats[256 + j], acc);
}

__global__ void k_norm_elu(const float* __restrict__ X, const float* __restrict__ w,
                           const float* __restrict__ bb, float* out, int cm, int n) {
    int i = blockIdx.x * blockDim.x + threadIdx.x;
    int st = gridDim.x * blockDim.x;
    for (; i < n; i += st) {
        int j = i & cm;
        float rstd = rsqrtf(g_colstats[256 + j] * (1.0f / NN) + EPSN);
        float y = w[j] * X[i] * rstd + bb[j];
        out[i] = y > 0.f ? y : expm1f(y);
    }
}

// ---------------- layer2 GEMM: h2[N,128] = h1n[N,256] @ W2[256,128] ----------
__global__ void k_gemm2(const float* __restrict__ W2) {
    int r0 = blockIdx.x * 32;
    int c = threadIdx.x;      // 128 threads = 128 output columns
    __shared__ float xs[32 * 256];
    for (int idx = c; idx < 32 * 256; idx += 128) {
        int r = idx >> 8, k = idx & 255;
        int row = r0 + r;
        xs[idx] = (row < NN) ? g_A[(size_t)row * 256 + k] : 0.f;
    }
    __syncthreads();
    float acc[32];
#pragma unroll
    for (int r = 0; r < 32; r++) acc[r] = 0.f;
    for (int k = 0; k < 256; k++) {
        float wv = W2[k * 128 + c];
#pragma unroll
        for (int r = 0; r < 32; r++) acc[r] += xs[r * 256 + k] * wv;
    }
#pragma unroll
    for (int r = 0; r < 32; r++) {
        int row = r0 + r;
        if (row < NN) g_B[(size_t)row * 128 + c] = acc[r];
    }
}

// ---------------- per-node attention logits, layer2 --------------------------
__global__ void k_al2(const float* __restrict__ as2, const float* __restrict__ ad2) {
    int n = blockIdx.x;
    int j = threadIdx.x;  // 128
    float h = g_B[(size_t)n * 128 + j];
    float vs = h * as2[j];
    float vd = h * ad2[j];
    for (int o = 16; o; o >>= 1) {
        vs += __shfl_down_sync(0xFFFFFFFFu, vs, o);
        vd += __shfl_down_sync(0xFFFFFFFFu, vd, o);
    }
    __shared__ float sS[4], sD[4];
    int lane = j & 31, wid = j >> 5;
    if (lane == 0) { sS[wid] = vs; sD[wid] = vd; }
    __syncthreads();
    if (j < 2) {
        g_alS[n * 2 + j] = sS[2 * j] + sS[2 * j + 1];
        g_alD[n * 2 + j] = sD[2 * j] + sD[2 * j + 1];
    }
}

__global__ void k_alpha2(const int* __restrict__ ei, const float* __restrict__ ea) {
    int idx = blockIdx.x * blockDim.x + threadIdx.x;
    if (idx >= ET * 2) return;
    int e = idx >> 1, h = idx & 1;
    int s, d;
    float ale;
    if (e < EE) {
        s = ei[e]; d = ei[EE + e];
        float e0 = ea[2 * e], e1 = ea[2 * e + 1];
        ale = e0 * g_v2[2 * h] + e1 * g_v2[2 * h + 1];
    } else {
        s = e - EE; d = s; ale = g_la2[h];
    }
    float a = g_alS[s * 2 + h] + g_alD[d * 2 + h] + ale;
    a = a > 0.f ? a : 0.2f * a;
    float ex = __expf(a);
    g_alpha[idx] = ex;
    atomicAdd(&g_den[d * 2 + h], ex);
}

__global__ void k_msg2(const int* __restrict__ ei) {
    int e = blockIdx.x;
    int j = threadIdx.x;  // 128
    __shared__ float w[2];
    __shared__ int sh_s, sh_d;
    if (j == 0) {
        int s, d;
        if (e < EE) { s = ei[e]; d = ei[EE + e]; } else { s = e - EE; d = s; }
        sh_s = s; sh_d = d;
        w[0] = g_alpha[e * 2 + 0] / g_den[d * 2 + 0];
        w[1] = g_alpha[e * 2 + 1] / g_den[d * 2 + 1];
    }
    __syncthreads();
    atomicAdd(&g_B[(size_t)NN * 128 + (size_t)sh_d * 128 + j],
              g_B[(size_t)sh_s * 128 + j] * w[j >> 6]);
}

// ---------------- classifier: out[N,13] = h2n @ Wc + bc ----------------------
__global__ void k_cls(const float* __restrict__ Wc, const float* __restrict__ bc,
                      float* __restrict__ out) {
    int i = blockIdx.x * blockDim.x + threadIdx.x;
    int st = gridDim.x * blockDim.x;
    for (; i < NN * 13; i += st) {
        int n = i / 13;
        int c = i - n * 13;
        const float* hr = g_A + (size_t)n * 128;
        float acc = bc[c];
#pragma unroll 4
        for (int k = 0; k < 128; k++) acc += hr[k] * Wc[k * 13 + c];
        out[i] = acc;
    }
}

// ---------------- launch ------------------------------------------------------
extern "C" void kernel_launch(void* const* d_in, const int* in_sizes, int n_in,
                              void* d_out, int out_size) {
    const float* x    = (const float*)d_in[0];
    const int*   ei   = (const int*)d_in[1];
    const float* ea   = (const float*)d_in[2];
    const float* W1   = (const float*)d_in[3];
    const float* We1  = (const float*)d_in[4];
    const float* as1  = (const float*)d_in[5];
    const float* ad1  = (const float*)d_in[6];
    const float* ae1  = (const float*)d_in[7];
    const float* b1   = (const float*)d_in[8];
    const float* gn1w = (const float*)d_in[9];
    const float* gn1b = (const float*)d_in[10];
    const float* gn1m = (const float*)d_in[11];
    const float* W2   = (const float*)d_in[12];
    const float* We2  = (const float*)d_in[13];
    const float* as2  = (const float*)d_in[14];
    const float* ad2  = (const float*)d_in[15];
    const float* ae2  = (const float*)d_in[16];
    const float* b2   = (const float*)d_in[17];
    const float* gn2w = (const float*)d_in[18];
    const float* gn2b = (const float*)d_in[19];
    const float* gn2m = (const float*)d_in[20];
    const float* Wc   = (const float*)d_in[21];
    const float* bc   = (const float*)d_in[22];
    float* out = (float*)d_out;

    float *pB, *pDen, *pEam, *pCol;
    cudaGetSymbolAddress((void**)&pB, g_B);
    cudaGetSymbolAddress((void**)&pDen, g_den);
    cudaGetSymbolAddress((void**)&pEam, g_eamsum);
    cudaGetSymbolAddress((void**)&pCol, g_colstats);

    // edge_attr mean + small precomputes
    k_zero<<<1, 64>>>(pEam, 2);
    k_eamean<<<256, 256>>>(ea);
    k_prep<<<1, 32>>>(We1, ae1, We2, ae2);

    // ---- layer 1 ----
    k_h1<<<NN, 256>>>(x, W1, as1, ad1);
    k_zero<<<512, 256>>>(pDen, NN * 4);
    k_alpha1<<<(ET * 4 + 255) / 256, 256>>>(ei, ea);
    k_zero<<<2048, 256>>>(pB, NN * 256);
    k_msg1<<<ET, 256>>>(ei);
    k_zero<<<1, 512>>>(pCol, 512);
    k_colsum<<<(NN + 127) / 128, 256>>>(pB, 256, 128);
    k_center_var<<<(NN + 127) / 128, 256>>>(pB, b1, gn1m, 256, 128);
    {
        float* pA; cudaGetSymbolAddress((void**)&pA, g_A);
        k_norm_elu<<<2048, 256>>>(pB, gn1w, gn1b, pA, 255, NN * 256);
    }

    // ---- layer 2 ----
    k_gemm2<<<(NN + 31) / 32, 128>>>(W2);
    k_al2<<<NN, 128>>>(as2, ad2);
    k_zero<<<512, 256>>>(pDen, NN * 2);
    k_alpha2<<<(ET * 2 + 255) / 256, 256>>>(ei, ea);
    k_zero<<<2048, 256>>>(pB + (size_t)NN * 128, NN * 128);
    k_msg2<<<ET, 128>>>(ei);
    k_zero<<<1, 512>>>(pCol, 512);
    k_colsum<<<(NN + 127) / 128, 128>>>(pB + (size_t)NN * 128, 128, 128);
    k_center_var<<<(NN + 127) / 128, 128>>>(pB + (size_t)NN * 128, b2, gn2m, 128, 128);
    {
        float* pA; cudaGetSymbolAddress((void**)&pA, g_A);
        k_norm_elu<<<2048, 256>>>(pB + (size_t)NN * 128, gn2w, gn2b, pA, 127, NN * 128);
    }

    // ---- classifier ----
    k_cls<<<(NN * 13 + 255) / 256, 256>>>(Wc, bc, out);
}

// round 2
// speedup vs baseline: 2.3468x; 2.3468x over previous
#include <cuda_runtime.h>
#include <cuda_bf16.h>
#include <math.h>

#define NN 50000
#define EE 400000
#define ET 450000   // EE + NN self loops
#define EPSN 1e-5f

// ---------------- scratch (device globals) -----------------------------------
__device__ float g_A[(size_t)NN * 256];       // h1 -> h1n -> h2n
__device__ float g_B[(size_t)NN * 256];       // gat1 out | [h2 (128) ...][gat2 out at +NN*128]
__device__ float g_alpha[(size_t)ET * 4];     // exp(alpha) per CSR pos (layer2 stride 2)
__device__ float g_alS[(size_t)NN * 4];
__device__ float g_alD[(size_t)NN * 4];
__device__ float g_colstats[512];             // [0:256) colsum, [256:512) colsumsq
__device__ float g_cscale[256];
__device__ float g_cshift[256];
__device__ float g_eamsum[2];
__device__ float g_v1[8];                     // edge-attr attention vectors
__device__ float g_v2[4];
__device__ float g_la1[4];                    // self-loop al_e
__device__ float g_la2[2];
__device__ float g_uS1[12], g_uD1[12];        // [f*4+h]  f<3,h<4
__device__ float g_uS2[512], g_uD2[512];      // [k*2+h]  k<256,h<2
// CSR
__device__ int g_cnt[NN];
__device__ int g_rowptr[NN + 1];
__device__ int g_part[256];
__device__ int g_csr_src[ET];
__device__ int g_csr_e[ET];

// ---------------- utility ----------------------------------------------------
__global__ void k_zero(float* p, int n) {
    int i = blockIdx.x * blockDim.x + threadIdx.x;
    int st = gridDim.x * blockDim.x;
    for (; i < n; i += st) p[i] = 0.f;
}
__global__ void k_zero2i(int* p1, int n1, float* p2, int n2) {
    int i = blockIdx.x * blockDim.x + threadIdx.x;
    int st = gridDim.x * blockDim.x;
    for (int k = i; k < n1; k += st) p1[k] = 0;
    for (int k = i; k < n2; k += st) p2[k] = 0.f;
}
__global__ void k_zeroi(int* p, int n) {
    int i = blockIdx.x * blockDim.x + threadIdx.x;
    int st = gridDim.x * blockDim.x;
    for (; i < n; i += st) p[i] = 0;
}

// ---------------- edge_attr mean ---------------------------------------------
__global__ void k_eamean(const float* __restrict__ ea) {
    float s0 = 0.f, s1 = 0.f;
    for (int e = blockIdx.x * blockDim.x + threadIdx.x; e < EE; e += gridDim.x * blockDim.x) {
        s0 += ea[2 * e];
        s1 += ea[2 * e + 1];
    }
    for (int o = 16; o; o >>= 1) {
        s0 += __shfl_down_sync(0xFFFFFFFFu, s0, o);
        s1 += __shfl_down_sync(0xFFFFFFFFu, s1, o);
    }
    __shared__ float sh[16];
    int lane = threadIdx.x & 31, wid = threadIdx.x >> 5;
    if (lane == 0) { sh[wid] = s0; sh[8 + wid] = s1; }
    __syncthreads();
    if (threadIdx.x == 0) {
        float a = 0.f, b = 0.f;
        for (int w = 0; w < 8; w++) { a += sh[w]; b += sh[8 + w]; }
        atomicAdd(&g_eamsum[0], a);
        atomicAdd(&g_eamsum[1], b);
    }
}

// ---------------- CSR build --------------------------------------------------
__global__ void k_count(const int* __restrict__ ei) {
    int e = blockIdx.x * blockDim.x + threadIdx.x;
    if (e >= ET) return;
    int d = (e < EE) ? ei[EE + e] : (e - EE);
    atomicAdd(&g_cnt[d], 1);
}

__global__ void k_scan_block() {
    __shared__ int sh[256];
    int i = blockIdx.x * 256 + threadIdx.x;
    int v = (i < NN) ? g_cnt[i] : 0;
    sh[threadIdx.x] = v;
    __syncthreads();
    for (int o = 1; o < 256; o <<= 1) {
        int t = (threadIdx.x >= o) ? sh[threadIdx.x - o] : 0;
        __syncthreads();
        sh[threadIdx.x] += t;
        __syncthreads();
    }
    if (i < NN) g_rowptr[i] = sh[threadIdx.x] - v;   // exclusive within block
    if (threadIdx.x == 255) g_part[blockIdx.x] = sh[255];
}

__global__ void k_scan_part(int nb) {
    __shared__ int sh[256];
    int t = threadIdx.x;
    int v = (t < nb) ? g_part[t] : 0;
    sh[t] = v;
    __syncthreads();
    for (int o = 1; o < 256; o <<= 1) {
        int u = (t >= o) ? sh[t - o] : 0;
        __syncthreads();
        sh[t] += u;
        __syncthreads();
    }
    if (t < nb) g_part[t] = sh[t] - v;   // exclusive
}

__global__ void k_scan_add() {
    int i = blockIdx.x * 256 + threadIdx.x;
    if (i < NN) g_rowptr[i] += g_part[blockIdx.x];
    if (i == 0) g_rowptr[NN] = ET;
}

__global__ void k_fill(const int* __restrict__ ei) {
    int e = blockIdx.x * blockDim.x + threadIdx.x;
    if (e >= ET) return;
    int s, d;
    if (e < EE) { s = ei[e]; d = ei[EE + e]; } else { s = e - EE; d = s; }
    int pos = g_rowptr[d] + atomicAdd(&g_cnt[d], 1);
    g_csr_src[pos] = s;
    g_csr_e[pos] = e;
}

// ---------------- small precomputes ------------------------------------------
__global__ void k_prep(const float* __restrict__ We1, const float* __restrict__ ae1,
                       const float* __restrict__ We2, const float* __restrict__ ae2,
                       const float* __restrict__ W1, const float* __restrict__ as1,
                       const float* __restrict__ ad1) {
    int t = threadIdx.x;
    if (t < 8) {                    // v1[h*2+f]
        int h = t >> 1, f = t & 1;
        float s = 0.f;
        for (int d = 0; d < 64; d++) s += We1[f * 256 + h * 64 + d] * ae1[h * 64 + d];
        g_v1[t] = s;
    } else if (t < 12) {            // v2
        int tt = t - 8, h = tt >> 1, f = tt & 1;
        float s = 0.f;
        for (int d = 0; d < 64; d++) s += We2[f * 128 + h * 64 + d] * ae2[h * 64 + d];
        g_v2[tt] = s;
    } else if (t < 24) {            // uS1[f*4+h]
        int idx = t - 12, f = idx >> 2, h = idx & 3;
        float s = 0.f;
        for (int d = 0; d < 64; d++) s += W1[f * 256 + h * 64 + d] * as1[h * 64 + d];
        g_uS1[idx] = s;
    } else if (t < 36) {            // uD1
        int idx = t - 24, f = idx >> 2, h = idx & 3;
        float s = 0.f;
        for (int d = 0; d < 64; d++) s += W1[f * 256 + h * 64 + d] * ad1[h * 64 + d];
        g_uD1[idx] = s;
    }
    __syncthreads();
    if (t == 0) {
        float e0 = g_eamsum[0] / (float)EE;
        float e1 = g_eamsum[1] / (float)EE;
        for (int h = 0; h < 4; h++) g_la1[h] = e0 * g_v1[2 * h] + e1 * g_v1[2 * h + 1];
        for (int h = 0; h < 2; h++) g_la2[h] = e0 * g_v2[2 * h] + e1 * g_v2[2 * h + 1];
    }
}

__global__ void k_prep2(const float* __restrict__ W2, const float* __restrict__ as2,
                        const float* __restrict__ ad2) {
    int t = blockIdx.x * blockDim.x + threadIdx.x;
    if (t >= 1024) return;
    int which = t >> 9;
    int kk = (t & 511) >> 1, h = t & 1;
    const float* a = which ? ad2 : as2;
    float s = 0.f;
    for (int d = 0; d < 64; d++) s += W2[kk * 128 + h * 64 + d] * a[h * 64 + d];
    if (which) g_uD2[kk * 2 + h] = s; else g_uS2[kk * 2 + h] = s;
}

// ---------------- layer1: h1 = x @ W1 (pure elementwise) ---------------------
__global__ void k_h1w(const float* __restrict__ x, const float* __restrict__ W1) {
    __shared__ float w[768];
    if (threadIdx.x < 256) {
        w[threadIdx.x] = W1[threadIdx.x];
        w[256 + threadIdx.x] = W1[256 + threadIdx.x];
        w[512 + threadIdx.x] = W1[512 + threadIdx.x];
    }
    __syncthreads();
    int i = blockIdx.x * blockDim.x + threadIdx.x;
    int st = gridDim.x * blockDim.x;
    for (; i < NN * 256; i += st) {
        int n = i >> 8, j = i & 255;
        float x0 = __ldg(&x[3 * n]), x1 = __ldg(&x[3 * n + 1]), x2 = __ldg(&x[3 * n + 2]);
        g_A[i] = x0 * w[j] + x1 * w[256 + j] + x2 * w[512 + j];
    }
}

__global__ void k_al1(const float* __restrict__ x) {
    int n = blockIdx.x * blockDim.x + threadIdx.x;
    if (n >= NN) return;
    float x0 = x[3 * n], x1 = x[3 * n + 1], x2 = x[3 * n + 2];
#pragma unroll
    for (int h = 0; h < 4; h++) {
        g_alS[n * 4 + h] = x0 * g_uS1[h] + x1 * g_uS1[4 + h] + x2 * g_uS1[8 + h];
        g_alD[n * 4 + h] = x0 * g_uD1[h] + x1 * g_uD1[4 + h] + x2 * g_uD1[8 + h];
    }
}

// ---------------- fused GAT aggregation, layer1 (block per dst node) ---------
__global__ void k_agg1(const float* __restrict__ ea) {
    int d = blockIdx.x;
    int j = threadIdx.x;   // 256
    int p0 = g_rowptr[d], p1 = g_rowptr[d + 1];
    __shared__ float sv[8], sla[4], sden[4], rden[4];
    __shared__ float ws[256];
    __shared__ int ssrc[64];
    if (j < 8) sv[j] = g_v1[j];
    if (j < 4) { sla[j] = g_la1[j]; sden[j] = 0.f; }
    __syncthreads();

    float aD0 = g_alD[d * 4], aD1 = g_alD[d * 4 + 1], aD2 = g_alD[d * 4 + 2], aD3 = g_alD[d * 4 + 3];
    float den0 = 0.f, den1 = 0.f, den2 = 0.f, den3 = 0.f;
    for (int pos = p0 + j; pos < p1; pos += 256) {
        int e = g_csr_e[pos];
        int s = g_csr_src[pos];
        float ale0, ale1, ale2, ale3;
        if (e < EE) {
            float e0 = ea[2 * e], e1 = ea[2 * e + 1];
            ale0 = e0 * sv[0] + e1 * sv[1];
            ale1 = e0 * sv[2] + e1 * sv[3];
            ale2 = e0 * sv[4] + e1 * sv[5];
            ale3 = e0 * sv[6] + e1 * sv[7];
        } else {
            ale0 = sla[0]; ale1 = sla[1]; ale2 = sla[2]; ale3 = sla[3];
        }
        float a0 = g_alS[s * 4 + 0] + aD0 + ale0;
        float a1 = g_alS[s * 4 + 1] + aD1 + ale1;
        float a2 = g_alS[s * 4 + 2] + aD2 + ale2;
        float a3 = g_alS[s * 4 + 3] + aD3 + ale3;
        a0 = a0 > 0.f ? a0 : 0.2f * a0;
        a1 = a1 > 0.f ? a1 : 0.2f * a1;
        a2 = a2 > 0.f ? a2 : 0.2f * a2;
        a3 = a3 > 0.f ? a3 : 0.2f * a3;
        float x0 = __expf(a0), x1 = __expf(a1), x2 = __expf(a2), x3 = __expf(a3);
        g_alpha[pos * 4 + 0] = x0; den0 += x0;
        g_alpha[pos * 4 + 1] = x1; den1 += x1;
        g_alpha[pos * 4 + 2] = x2; den2 += x2;
        g_alpha[pos * 4 + 3] = x3; den3 += x3;
    }
    for (int o = 16; o; o >>= 1) {
        den0 += __shfl_down_sync(0xFFFFFFFFu, den0, o);
        den1 += __shfl_down_sync(0xFFFFFFFFu, den1, o);
        den2 += __shfl_down_sync(0xFFFFFFFFu, den2, o);
        den3 += __shfl_down_sync(0xFFFFFFFFu, den3, o);
    }
    if ((j & 31) == 0) {
        atomicAdd(&sden[0], den0);
        atomicAdd(&sden[1], den1);
        atomicAdd(&sden[2], den2);
        atomicAdd(&sden[3], den3);
    }
    __syncthreads();
    if (j < 4) rden[j] = 1.f / sden[j];
    __syncthreads();

    float acc = 0.f;
    int hsel = j >> 6;
    for (int base = p0; base < p1; base += 64) {
        int m = min(64, p1 - base);
        if (j < m * 4) ws[j] = g_alpha[base * 4 + j] * rden[j & 3];
        if (j < m) ssrc[j] = g_csr_src[base + j];
        __syncthreads();
        for (int i = 0; i < m; i++)
            acc += g_A[(size_t)ssrc[i] * 256 + j] * ws[i * 4 + hsel];
        __syncthreads();
    }
    g_B[(size_t)d * 256 + j] = acc;
}

// ---------------- GraphNorm: fused stats + apply -----------------------------
__global__ void k_colsum2(const float* __restrict__ X, int C, int rpb) {
    int j = threadIdx.x;
    int r0 = blockIdx.x * rpb, r1 = min(r0 + rpb, NN);
    float s = 0.f, q = 0.f;
    for (int r = r0; r < r1; r++) {
        float v = X[(size_t)r * C + j];
        s += v;
        q += v * v;
    }
    atomicAdd(&g_colstats[j], s);
    atomicAdd(&g_colstats[256 + j], q);
}

__global__ void k_stats(const float* __restrict__ b, const float* __restrict__ ms,
                        const float* __restrict__ w, const float* __restrict__ gb, int C) {
    int j = threadIdx.x;
    if (j >= C) return;
    float invN = 1.0f / NN;
    float sum = g_colstats[j], sq = g_colstats[256 + j];
    float m = sum * invN + b[j];
    float cp = b[j] - m * ms[j];
    float var = sq * invN + 2.f * cp * (sum * invN) + cp * cp;
    float rstd = rsqrtf(var + EPSN);
    g_cscale[j] = w[j] * rstd;
    g_cshift[j] = cp * w[j] * rstd + gb[j];
}

__global__ void k_napply(const float* __restrict__ X, float* __restrict__ out, int cm, int n) {
    int i = blockIdx.x * blockDim.x + threadIdx.x;
    int st = gridDim.x * blockDim.x;
    for (; i < n; i += st) {
        int j = i & cm;
        float y = X[i] * g_cscale[j] + g_cshift[j];
        out[i] = y > 0.f ? y : expm1f(y);
    }
}

// ---------------- layer2 GEMM: h2[N,128] = h1n[N,256] @ W2[256,128] ----------
__global__ void k_gemm2(const float* __restrict__ W2) {
    int r0 = blockIdx.x * 32;
    int c = threadIdx.x & 127;
    int rh = threadIdx.x >> 7;   // 0/1 -> rows [0,16) / [16,32)
    __shared__ float xs[32 * 256];
    for (int idx = threadIdx.x; idx < 32 * 256; idx += 256) {
        int r = idx >> 8, k = idx & 255;
        int row = r0 + r;
        xs[idx] = (row < NN) ? g_A[(size_t)row * 256 + k] : 0.f;
    }
    __syncthreads();
    float acc[16];
#pragma unroll
    for (int i = 0; i < 16; i++) acc[i] = 0.f;
    const float4* xs4 = (const float4*)xs;
    for (int k0 = 0; k0 < 256; k0 += 4) {
        float w0 = W2[(k0 + 0) * 128 + c];
        float w1 = W2[(k0 + 1) * 128 + c];
        float w2 = W2[(k0 + 2) * 128 + c];
        float w3 = W2[(k0 + 3) * 128 + c];
#pragma unroll
        for (int r = 0; r < 16; r++) {
            float4 a = xs4[(rh * 16 + r) * 64 + (k0 >> 2)];
            acc[r] += a.x * w0 + a.y * w1 + a.z * w2 + a.w * w3;
        }
    }
#pragma unroll
    for (int r = 0; r < 16; r++) {
        int row = r0 + rh * 16 + r;
        if (row < NN) g_B[(size_t)row * 128 + c] = acc[r];
    }
}

// ---------------- layer2 attention logits (warp per node) --------------------
__global__ void k_al2() {
    __shared__ float us[512], ud[512];
    for (int i = threadIdx.x; i < 512; i += 256) { us[i] = g_uS2[i]; ud[i] = g_uD2[i]; }
    __syncthreads();
    int warp = (blockIdx.x * 256 + threadIdx.x) >> 5;
    int lane = threadIdx.x & 31;
    int nw = (gridDim.x * 256) >> 5;
    for (int n = warp; n < NN; n += nw) {
        const float* row = g_A + (size_t)n * 256;
        float s0 = 0.f, s1 = 0.f, d0 = 0.f, d1 = 0.f;
        for (int k = lane; k < 256; k += 32) {
            float h = row[k];
            s0 += h * us[k * 2];
            s1 += h * us[k * 2 + 1];
            d0 += h * ud[k * 2];
            d1 += h * ud[k * 2 + 1];
        }
        for (int o = 16; o; o >>= 1) {
            s0 += __shfl_down_sync(0xFFFFFFFFu, s0, o);
            s1 += __shfl_down_sync(0xFFFFFFFFu, s1, o);
            d0 += __shfl_down_sync(0xFFFFFFFFu, d0, o);
            d1 += __shfl_down_sync(0xFFFFFFFFu, d1, o);
        }
        if (lane == 0) {
            g_alS[n * 2] = s0; g_alS[n * 2 + 1] = s1;
            g_alD[n * 2] = d0; g_alD[n * 2 + 1] = d1;
        }
    }
}

// ---------------- fused GAT aggregation, layer2 ------------------------------
__global__ void k_agg2(const float* __restrict__ ea) {
    int d = blockIdx.x;
    int j = threadIdx.x;   // 128
    int p0 = g_rowptr[d], p1 = g_rowptr[d + 1];
    __shared__ float sv[4], sla[2], sden[2], rden[2];
    __shared__ float ws[128];
    __shared__ int ssrc[64];
    if (j < 4) sv[j] = g_v2[j];
    if (j < 2) { sla[j] = g_la2[j]; sden[j] = 0.f; }
    __syncthreads();

    float aD0 = g_alD[d * 2], aD1 = g_alD[d * 2 + 1];
    float den0 = 0.f, den1 = 0.f;
    for (int pos = p0 + j; pos < p1; pos += 128) {
        int e = g_csr_e[pos];
        int s = g_csr_src[pos];
        float ale0, ale1;
        if (e < EE) {
            float e0 = ea[2 * e], e1 = ea[2 * e + 1];
            ale0 = e0 * sv[0] + e1 * sv[1];
            ale1 = e0 * sv[2] + e1 * sv[3];
        } else {
            ale0 = sla[0]; ale1 = sla[1];
        }
        float a0 = g_alS[s * 2 + 0] + aD0 + ale0;
        float a1 = g_alS[s * 2 + 1] + aD1 + ale1;
        a0 = a0 > 0.f ? a0 : 0.2f * a0;
        a1 = a1 > 0.f ? a1 : 0.2f * a1;
        float x0 = __expf(a0), x1 = __expf(a1);
        g_alpha[pos * 2 + 0] = x0; den0 += x0;
        g_alpha[pos * 2 + 1] = x1; den1 += x1;
    }
    for (int o = 16; o; o >>= 1) {
        den0 += __shfl_down_sync(0xFFFFFFFFu, den0, o);
        den1 += __shfl_down_sync(0xFFFFFFFFu, den1, o);
    }
    if ((j & 31) == 0) {
        atomicAdd(&sden[0], den0);
        atomicAdd(&sden[1], den1);
    }
    __syncthreads();
    if (j < 2) rden[j] = 1.f / sden[j];
    __syncthreads();

    float acc = 0.f;
    int hsel = j >> 6;
    for (int base = p0; base < p1; base += 64) {
        int m = min(64, p1 - base);
        if (j < m * 2) ws[j] = g_alpha[base * 2 + j] * rden[j & 1];
        if (j < m) ssrc[j] = g_csr_src[base + j];
        __syncthreads();
        for (int i = 0; i < m; i++)
            acc += g_B[(size_t)ssrc[i] * 128 + j] * ws[i * 2 + hsel];
        __syncthreads();
    }
    g_B[(size_t)NN * 128 + (size_t)d * 128 + j] = acc;
}

// ---------------- classifier (warp per node) ---------------------------------
__global__ void k_cls(const float* __restrict__ Wc, const float* __restrict__ bc,
                      float* __restrict__ out) {
    __shared__ float wc[128 * 13];
    __shared__ float sbc[13];
    for (int i = threadIdx.x; i < 128 * 13; i += 256) wc[i] = Wc[i];
    if (threadIdx.x < 13) sbc[threadIdx.x] = bc[threadIdx.x];
    __syncthreads();
    int warp = (blockIdx.x * 256 + threadIdx.x) >> 5;
    int lane = threadIdx.x & 31;
    int nw = (gridDim.x * 256) >> 5;
    for (int n = warp; n < NN; n += nw) {
        float4 hv = *(const float4*)(g_A + (size_t)n * 128 + lane * 4);
        int kb = lane * 4;
#pragma unroll
        for (int c = 0; c < 13; c++) {
            float p = hv.x * wc[kb * 13 + c] + hv.y * wc[(kb + 1) * 13 + c]
                    + hv.z * wc[(kb + 2) * 13 + c] + hv.w * wc[(kb + 3) * 13 + c];
            for (int o = 16; o; o >>= 1) p += __shfl_down_sync(0xFFFFFFFFu, p, o);
            if (lane == 0) out[n * 13 + c] = p + sbc[c];
        }
    }
}

// ---------------- launch ------------------------------------------------------
extern "C" void kernel_launch(void* const* d_in, const int* in_sizes, int n_in,
                              void* d_out, int out_size) {
    const float* x    = (const float*)d_in[0];
    const int*   ei   = (const int*)d_in[1];
    const float* ea   = (const float*)d_in[2];
    const float* W1   = (const float*)d_in[3];
    const float* We1  = (const float*)d_in[4];
    const float* as1  = (const float*)d_in[5];
    const float* ad1  = (const float*)d_in[6];
    const float* ae1  = (const float*)d_in[7];
    const float* b1   = (const float*)d_in[8];
    const float* gn1w = (const float*)d_in[9];
    const float* gn1b = (const float*)d_in[10];
    const float* gn1m = (const float*)d_in[11];
    const float* W2   = (const float*)d_in[12];
    const float* We2  = (const float*)d_in[13];
    const float* as2  = (const float*)d_in[14];
    const float* ad2  = (const float*)d_in[15];
    const float* ae2  = (const float*)d_in[16];
    const float* b2   = (const float*)d_in[17];
    const float* gn2w = (const float*)d_in[18];
    const float* gn2b = (const float*)d_in[19];
    const float* gn2m = (const float*)d_in[20];
    const float* Wc   = (const float*)d_in[21];
    const float* bc   = (const float*)d_in[22];
    float* out = (float*)d_out;

    float *pB, *pEam, *pCol;
    int* pCnt;
    cudaGetSymbolAddress((void**)&pB, g_B);
    cudaGetSymbolAddress((void**)&pEam, g_eamsum);
    cudaGetSymbolAddress((void**)&pCol, g_colstats);
    cudaGetSymbolAddress((void**)&pCnt, g_cnt);
    float* pA;
    cudaGetSymbolAddress((void**)&pA, g_A);

    int nb = (NN + 255) / 256;   // 196 scan blocks

    // ---- CSR build + precomputes ----
    k_zero2i<<<128, 256>>>(pCnt, NN, pEam, 2);
    k_eamean<<<256, 256>>>(ea);
    k_count<<<(ET + 255) / 256, 256>>>(ei);
    k_scan_block<<<nb, 256>>>();
    k_scan_part<<<1, 256>>>(nb);
    k_scan_add<<<nb, 256>>>();
    k_zeroi<<<128, 256>>>(pCnt, NN);
    k_fill<<<(ET + 255) / 256, 256>>>(ei);
    k_prep<<<1, 64>>>(We1, ae1, We2, ae2, W1, as1, ad1);
    k_prep2<<<4, 256>>>(W2, as2, ad2);

    // ---- layer 1 ----
    k_h1w<<<2048, 256>>>(x, W1);
    k_al1<<<(NN + 255) / 256, 256>>>(x);
    k_agg1<<<NN, 256>>>(ea);
    k_zero<<<2, 256>>>(pCol, 512);
    k_colsum2<<<(NN + 127) / 128, 256>>>(pB, 256, 128);
    k_stats<<<1, 256>>>(b1, gn1m, gn1w, gn1b, 256);
    k_napply<<<2048, 256>>>(pB, pA, 255, NN * 256);

    // ---- layer 2 ----
    k_gemm2<<<(NN + 31) / 32, 256>>>(W2);
    k_al2<<<512, 256>>>();
    k_agg2<<<NN, 128>>>(ea);
    k_zero<<<2, 256>>>(pCol, 512);
    k_colsum2<<<(NN + 127) / 128, 128>>>(pB + (size_t)NN * 128, 128, 128);
    k_stats<<<1, 256>>>(b2, gn2m, gn2w, gn2b, 128);
    k_napply<<<2048, 256>>>(pB + (size_t)NN * 128, pA, 127, NN * 128);

    // ---- classifier ----
    k_cls<<<512, 256>>>(Wc, bc, out);
}

// round 3
// speedup vs baseline: 2.6307x; 1.1210x over previous
#include <cuda_runtime.h>
#include <cuda_bf16.h>
#include <math.h>

#define NN 50000
#define EE 400000
#define ET 450000   // EE + NN self loops
#define EPSN 1e-5f
#define XPAD 65     // xs k-major row stride (floats) to dodge bank conflicts

// ---------------- scratch (device globals) -----------------------------------
__device__ float g_A[(size_t)NN * 256];       // h1 (raw) -> h2
__device__ float g_B[(size_t)NN * 256];       // gat1 raw | [.. gat2 raw at +NN*128]
__device__ float g_alpha[(size_t)ET * 4];
__device__ float g_alS[(size_t)NN * 4];
__device__ float g_alD[(size_t)NN * 4];
__device__ float g_colstats[512];
__device__ float g_cscale[256];
__device__ float g_cshift[256];
__device__ float g_eamsum[2];
__device__ float g_v1[8];
__device__ float g_v2[4];
__device__ float g_la1[4];
__device__ float g_la2[2];
__device__ float g_uS1[12], g_uD1[12];
__device__ float g_uS2[512], g_uD2[512];      // [k*2+h]
// CSR
__device__ int g_cnt[NN];
__device__ int g_rowptr[NN + 1];
__device__ int g_part[256];
__device__ int g_csr_src[ET];
__device__ int g_csr_e[ET];

// f32x2 packed helpers
#define FMA2(acc, a, b) asm("fma.rn.f32x2 %0, %1, %2, %0;" : "+l"(acc) : "l"(a), "l"(b))
#define BCAST2(p, f)    asm("mov.b64 %0, {%1, %1};" : "=l"(p) : "f"(f))
#define PACK2(p, lo, hi) asm("mov.b64 %0, {%1, %2};" : "=l"(p) : "f"(lo), "f"(hi))
#define UNPK2(lo, hi, p) asm("mov.b64 {%0, %1}, %2;" : "=f"(lo), "=f"(hi) : "l"(p))

// ---------------- utility ----------------------------------------------------
__global__ void k_zero(float* p, int n) {
    int i = blockIdx.x * blockDim.x + threadIdx.x;
    int st = gridDim.x * blockDim.x;
    for (; i < n; i += st) p[i] = 0.f;
}
__global__ void k_zero2i(int* p1, int n1, float* p2, int n2) {
    int i = blockIdx.x * blockDim.x + threadIdx.x;
    int st = gridDim.x * blockDim.x;
    for (int k = i; k < n1; k += st) p1[k] = 0;
    for (int k = i; k < n2; k += st) p2[k] = 0.f;
}
__global__ void k_zeroi(int* p, int n) {
    int i = blockIdx.x * blockDim.x + threadIdx.x;
    int st = gridDim.x * blockDim.x;
    for (; i < n; i += st) p[i] = 0;
}

// ---------------- fused: dst-degree count + edge_attr mean -------------------
__global__ void k_cm(const int* __restrict__ ei, const float* __restrict__ ea) {
    float s0 = 0.f, s1 = 0.f;
    int st = gridDim.x * blockDim.x;
    for (int e = blockIdx.x * blockDim.x + threadIdx.x; e < ET; e += st) {
        int d = (e < EE) ? ei[EE + e] : (e - EE);
        atomicAdd(&g_cnt[d], 1);
        if (e < EE) { s0 += ea[2 * e]; s1 += ea[2 * e + 1]; }
    }
    for (int o = 16; o; o >>= 1) {
        s0 += __shfl_down_sync(0xFFFFFFFFu, s0, o);
        s1 += __shfl_down_sync(0xFFFFFFFFu, s1, o);
    }
    __shared__ float sh[16];
    int lane = threadIdx.x & 31, wid = threadIdx.x >> 5;
    if (lane == 0) { sh[wid] = s0; sh[8 + wid] = s1; }
    __syncthreads();
    if (threadIdx.x == 0) {
        float a = 0.f, b = 0.f;
        for (int w = 0; w < 8; w++) { a += sh[w]; b += sh[8 + w]; }
        atomicAdd(&g_eamsum[0], a);
        atomicAdd(&g_eamsum[1], b);
    }
}

// ---------------- CSR scan ---------------------------------------------------
__global__ void k_scan_block() {
    __shared__ int sh[256];
    int i = blockIdx.x * 256 + threadIdx.x;
    int v = (i < NN) ? g_cnt[i] : 0;
    sh[threadIdx.x] = v;
    __syncthreads();
    for (int o = 1; o < 256; o <<= 1) {
        int t = (threadIdx.x >= o) ? sh[threadIdx.x - o] : 0;
        __syncthreads();
        sh[threadIdx.x] += t;
        __syncthreads();
    }
    if (i < NN) g_rowptr[i] = sh[threadIdx.x] - v;
    if (threadIdx.x == 255) g_part[blockIdx.x] = sh[255];
}

__global__ void k_scan_part(int nb) {
    __shared__ int sh[256];
    int t = threadIdx.x;
    int v = (t < nb) ? g_part[t] : 0;
    sh[t] = v;
    __syncthreads();
    for (int o = 1; o < 256; o <<= 1) {
        int u = (t >= o) ? sh[t - o] : 0;
        __syncthreads();
        sh[t] += u;
        __syncthreads();
    }
    if (t < nb) g_part[t] = sh[t] - v;
}

__global__ void k_scan_add() {
    int i = blockIdx.x * 256 + threadIdx.x;
    if (i < NN) g_rowptr[i] += g_part[blockIdx.x];
    if (i == 0) g_rowptr[NN] = ET;
}

__global__ void k_fill(const int* __restrict__ ei) {
    int e = blockIdx.x * blockDim.x + threadIdx.x;
    if (e >= ET) return;
    int s, d;
    if (e < EE) { s = ei[e]; d = ei[EE + e]; } else { s = e - EE; d = s; }
    int pos = g_rowptr[d] + atomicAdd(&g_cnt[d], 1);
    g_csr_src[pos] = s;
    g_csr_e[pos] = e;
}

// ---------------- small precomputes ------------------------------------------
__global__ void k_prep(const float* __restrict__ We1, const float* __restrict__ ae1,
                       const float* __restrict__ We2, const float* __restrict__ ae2,
                       const float* __restrict__ W1, const float* __restrict__ as1,
                       const float* __restrict__ ad1) {
    int t = threadIdx.x;
    if (t < 8) {
        int h = t >> 1, f = t & 1;
        float s = 0.f;
        for (int d = 0; d < 64; d++) s += We1[f * 256 + h * 64 + d] * ae1[h * 64 + d];
        g_v1[t] = s;
    } else if (t < 12) {
        int tt = t - 8, h = tt >> 1, f = tt & 1;
        float s = 0.f;
        for (int d = 0; d < 64; d++) s += We2[f * 128 + h * 64 + d] * ae2[h * 64 + d];
        g_v2[tt] = s;
    } else if (t < 24) {
        int idx = t - 12, f = idx >> 2, h = idx & 3;
        float s = 0.f;
        for (int d = 0; d < 64; d++) s += W1[f * 256 + h * 64 + d] * as1[h * 64 + d];
        g_uS1[idx] = s;
    } else if (t < 36) {
        int idx = t - 24, f = idx >> 2, h = idx & 3;
        float s = 0.f;
        for (int d = 0; d < 64; d++) s += W1[f * 256 + h * 64 + d] * ad1[h * 64 + d];
        g_uD1[idx] = s;
    }
    __syncthreads();
    if (t == 0) {
        float e0 = g_eamsum[0] / (float)EE;
        float e1 = g_eamsum[1] / (float)EE;
        for (int h = 0; h < 4; h++) g_la1[h] = e0 * g_v1[2 * h] + e1 * g_v1[2 * h + 1];
        for (int h = 0; h < 2; h++) g_la2[h] = e0 * g_v2[2 * h] + e1 * g_v2[2 * h + 1];
    }
}

__global__ void k_prep2(const float* __restrict__ W2, const float* __restrict__ as2,
                        const float* __restrict__ ad2) {
    int t = blockIdx.x * blockDim.x + threadIdx.x;
    if (t >= 1024) return;
    int which = t >> 9;
    int kk = (t & 511) >> 1, h = t & 1;
    const float* a = which ? ad2 : as2;
    float s = 0.f;
    for (int d = 0; d < 64; d++) s += W2[kk * 128 + h * 64 + d] * a[h * 64 + d];
    if (which) g_uD2[kk * 2 + h] = s; else g_uS2[kk * 2 + h] = s;
}

// ---------------- layer1: h1 = x @ W1 + fused attention logits ---------------
__global__ void k_h1w(const float* __restrict__ x, const float* __restrict__ W1) {
    __shared__ float w[768];
    __shared__ float su[24];
    if (threadIdx.x < 256) {
        w[threadIdx.x] = W1[threadIdx.x];
        w[256 + threadIdx.x] = W1[256 + threadIdx.x];
        w[512 + threadIdx.x] = W1[512 + threadIdx.x];
    }
    if (threadIdx.x < 12) { su[threadIdx.x] = g_uS1[threadIdx.x]; su[12 + threadIdx.x] = g_uD1[threadIdx.x]; }
    __syncthreads();
    int i = blockIdx.x * blockDim.x + threadIdx.x;
    int st = gridDim.x * blockDim.x;
    for (; i < NN * 64; i += st) {
        int n = i >> 6, j4 = (i & 63) * 4;
        float x0 = __ldg(&x[3 * n]), x1 = __ldg(&x[3 * n + 1]), x2 = __ldg(&x[3 * n + 2]);
        float4 o;
        o.x = x0 * w[j4 + 0] + x1 * w[256 + j4 + 0] + x2 * w[512 + j4 + 0];
        o.y = x0 * w[j4 + 1] + x1 * w[256 + j4 + 1] + x2 * w[512 + j4 + 1];
        o.z = x0 * w[j4 + 2] + x1 * w[256 + j4 + 2] + x2 * w[512 + j4 + 2];
        o.w = x0 * w[j4 + 3] + x1 * w[256 + j4 + 3] + x2 * w[512 + j4 + 3];
        *(float4*)(g_A + (size_t)n * 256 + j4) = o;
        if ((i & 63) == 0) {
#pragma unroll
            for (int h = 0; h < 4; h++) {
                g_alS[n * 4 + h] = x0 * su[h] + x1 * su[4 + h] + x2 * su[8 + h];
                g_alD[n * 4 + h] = x0 * su[12 + h] + x1 * su[16 + h] + x2 * su[20 + h];
            }
        }
    }
}

// ---------------- fused GAT aggregation, layer1 ------------------------------
__global__ void k_agg1(const float* __restrict__ ea) {
    int d = blockIdx.x;
    int j = threadIdx.x;   // 256
    int p0 = g_rowptr[d], p1 = g_rowptr[d + 1];
    __shared__ float sv[8], sla[4], sden[4], rden[4];
    __shared__ float ws[256];
    __shared__ int ssrc[64];
    if (j < 8) sv[j] = g_v1[j];
    if (j < 4) { sla[j] = g_la1[j]; sden[j] = 0.f; }
    __syncthreads();

    float aD0 = g_alD[d * 4], aD1 = g_alD[d * 4 + 1], aD2 = g_alD[d * 4 + 2], aD3 = g_alD[d * 4 + 3];
    float den0 = 0.f, den1 = 0.f, den2 = 0.f, den3 = 0.f;
    for (int pos = p0 + j; pos < p1; pos += 256) {
        int e = g_csr_e[pos];
        int s = g_csr_src[pos];
        float ale0, ale1, ale2, ale3;
        if (e < EE) {
            float e0 = ea[2 * e], e1 = ea[2 * e + 1];
            ale0 = e0 * sv[0] + e1 * sv[1];
            ale1 = e0 * sv[2] + e1 * sv[3];
            ale2 = e0 * sv[4] + e1 * sv[5];
            ale3 = e0 * sv[6] + e1 * sv[7];
        } else {
            ale0 = sla[0]; ale1 = sla[1]; ale2 = sla[2]; ale3 = sla[3];
        }
        float a0 = g_alS[s * 4 + 0] + aD0 + ale0;
        float a1 = g_alS[s * 4 + 1] + aD1 + ale1;
        float a2 = g_alS[s * 4 + 2] + aD2 + ale2;
        float a3 = g_alS[s * 4 + 3] + aD3 + ale3;
        a0 = a0 > 0.f ? a0 : 0.2f * a0;
        a1 = a1 > 0.f ? a1 : 0.2f * a1;
        a2 = a2 > 0.f ? a2 : 0.2f * a2;
        a3 = a3 > 0.f ? a3 : 0.2f * a3;
        float x0 = __expf(a0), x1 = __expf(a1), x2 = __expf(a2), x3 = __expf(a3);
        g_alpha[pos * 4 + 0] = x0; den0 += x0;
        g_alpha[pos * 4 + 1] = x1; den1 += x1;
        g_alpha[pos * 4 + 2] = x2; den2 += x2;
        g_alpha[pos * 4 + 3] = x3; den3 += x3;
    }
    for (int o = 16; o; o >>= 1) {
        den0 += __shfl_down_sync(0xFFFFFFFFu, den0, o);
        den1 += __shfl_down_sync(0xFFFFFFFFu, den1, o);
        den2 += __shfl_down_sync(0xFFFFFFFFu, den2, o);
        den3 += __shfl_down_sync(0xFFFFFFFFu, den3, o);
    }
    if ((j & 31) == 0) {
        atomicAdd(&sden[0], den0);
        atomicAdd(&sden[1], den1);
        atomicAdd(&sden[2], den2);
        atomicAdd(&sden[3], den3);
    }
    __syncthreads();
    if (j < 4) rden[j] = 1.f / sden[j];
    __syncthreads();

    float acc = 0.f;
    int hsel = j >> 6;
    for (int base = p0; base < p1; base += 64) {
        int m = min(64, p1 - base);
        if (j < m * 4) ws[j] = g_alpha[base * 4 + j] * rden[j & 3];
        if (j < m) ssrc[j] = g_csr_src[base + j];
        __syncthreads();
        for (int i = 0; i < m; i++)
            acc += g_A[(size_t)ssrc[i] * 256 + j] * ws[i * 4 + hsel];
        __syncthreads();
    }
    g_B[(size_t)d * 256 + j] = acc;
}

// ---------------- GraphNorm stats --------------------------------------------
__global__ void k_colsum2(const float* __restrict__ X, int C, int rpb) {
    int j = threadIdx.x;
    int r0 = blockIdx.x * rpb, r1 = min(r0 + rpb, NN);
    float s = 0.f, q = 0.f;
    for (int r = r0; r < r1; r++) {
        float v = X[(size_t)r * C + j];
        s += v;
        q += v * v;
    }
    atomicAdd(&g_colstats[j], s);
    atomicAdd(&g_colstats[256 + j], q);
}

__global__ void k_stats(const float* __restrict__ b, const float* __restrict__ ms,
                        const float* __restrict__ w, const float* __restrict__ gb, int C) {
    int j = threadIdx.x;
    if (j >= C) return;
    float invN = 1.0f / NN;
    float sum = g_colstats[j], sq = g_colstats[256 + j];
    float m = sum * invN + b[j];
    float cp = b[j] - m * ms[j];
    float var = sq * invN + 2.f * cp * (sum * invN) + cp * cp;
    float rstd = rsqrtf(var + EPSN);
    g_cscale[j] = w[j] * rstd;
    g_cshift[j] = cp * w[j] * rstd + gb[j];
}

// ---------------- fused GEMM2: norm+ELU on load, f32x2 FMA, logits epilogue --
// h2[N,128] = elu(norm(gat1)) @ W2 ; also alS2/alD2 logits.
__global__ void __launch_bounds__(256) k_gemm2f(const float* __restrict__ W2) {
    extern __shared__ float xs[];          // [256][XPAD] k-major
    __shared__ float cs[256], cf[256], us[512], ud[512];
    int tid = threadIdx.x;
    cs[tid] = g_cscale[tid];
    cf[tid] = g_cshift[tid];
    us[tid] = g_uS2[tid]; us[256 + tid] = g_uS2[256 + tid];
    ud[tid] = g_uD2[tid]; ud[256 + tid] = g_uD2[256 + tid];
    __syncthreads();

    int r0 = blockIdx.x * 64;
    // load + normalize + ELU + transpose into xs[k*XPAD + r]
    for (int idx = tid; idx < 64 * 64; idx += 256) {
        int r = idx >> 6;
        int kq = idx & 63;
        int row = r0 + r;
        float4 v = make_float4(0.f, 0.f, 0.f, 0.f);
        if (row < NN) v = *(const float4*)(g_B + (size_t)row * 256 + kq * 4);
        int k4 = kq * 4;
        float y0 = v.x * cs[k4 + 0] + cf[k4 + 0]; y0 = y0 > 0.f ? y0 : expm1f(y0);
        float y1 = v.y * cs[k4 + 1] + cf[k4 + 1]; y1 = y1 > 0.f ? y1 : expm1f(y1);
        float y2 = v.z * cs[k4 + 2] + cf[k4 + 2]; y2 = y2 > 0.f ? y2 : expm1f(y2);
        float y3 = v.w * cs[k4 + 3] + cf[k4 + 3]; y3 = y3 > 0.f ? y3 : expm1f(y3);
        xs[(k4 + 0) * XPAD + r] = y0;
        xs[(k4 + 1) * XPAD + r] = y1;
        xs[(k4 + 2) * XPAD + r] = y2;
        xs[(k4 + 3) * XPAD + r] = y3;
    }
    __syncthreads();

    int tx = tid & 31, ty = tid >> 5;
    int c0 = tx * 4, rb = ty * 8;
    unsigned long long acc[4][4];
#pragma unroll
    for (int p = 0; p < 4; p++)
#pragma unroll
        for (int c = 0; c < 4; c++) acc[p][c] = 0ull;

    const float* W2p = W2 + c0;
#pragma unroll 4
    for (int k = 0; k < 256; k++) {
        const float* xr = xs + k * XPAD + rb;
        float4 w = __ldg((const float4*)(W2p + k * 128));
        unsigned long long xp0, xp1, xp2, xp3;
        PACK2(xp0, xr[0], xr[1]);
        PACK2(xp1, xr[2], xr[3]);
        PACK2(xp2, xr[4], xr[5]);
        PACK2(xp3, xr[6], xr[7]);
        unsigned long long wp;
        BCAST2(wp, w.x);
        FMA2(acc[0][0], xp0, wp); FMA2(acc[1][0], xp1, wp); FMA2(acc[2][0], xp2, wp); FMA2(acc[3][0], xp3, wp);
        BCAST2(wp, w.y);
        FMA2(acc[0][1], xp0, wp); FMA2(acc[1][1], xp1, wp); FMA2(acc[2][1], xp2, wp); FMA2(acc[3][1], xp3, wp);
        BCAST2(wp, w.z);
        FMA2(acc[0][2], xp0, wp); FMA2(acc[1][2], xp1, wp); FMA2(acc[2][2], xp2, wp); FMA2(acc[3][2], xp3, wp);
        BCAST2(wp, w.w);
        FMA2(acc[0][3], xp0, wp); FMA2(acc[1][3], xp1, wp); FMA2(acc[2][3], xp2, wp); FMA2(acc[3][3], xp3, wp);
    }

    // store h2 -> g_A[N,128]
#pragma unroll
    for (int p = 0; p < 4; p++) {
        int row = r0 + rb + 2 * p;
        float l0, h0, l1, h1, l2, h2v, l3, h3;
        UNPK2(l0, h0, acc[p][0]);
        UNPK2(l1, h1, acc[p][1]);
        UNPK2(l2, h2v, acc[p][2]);
        UNPK2(l3, h3, acc[p][3]);
        if (row < NN)     *(float4*)(g_A + (size_t)row * 128 + c0)       = make_float4(l0, l1, l2, l3);
        if (row + 1 < NN) *(float4*)(g_A + (size_t)(row + 1) * 128 + c0) = make_float4(h0, h1, h2v, h3);
    }

    // epilogue: layer-2 attention logits from the normalized tile
    {
        int row = tid >> 2, q = tid & 3;
        int grow = r0 + row;
        const float* uu = (q < 2) ? (us + q) : (ud + (q - 2));
        float s = 0.f;
#pragma unroll 8
        for (int k = 0; k < 256; k++)
            s += xs[k * XPAD + row] * uu[k * 2];
        if (grow < NN) {
            if (q < 2) g_alS[grow * 2 + q] = s;
            else       g_alD[grow * 2 + (q - 2)] = s;
        }
    }
}

// ---------------- fused GAT aggregation, layer2 ------------------------------
__global__ void k_agg2(const float* __restrict__ ea) {
    int d = blockIdx.x;
    int j = threadIdx.x;   // 128
    int p0 = g_rowptr[d], p1 = g_rowptr[d + 1];
    __shared__ float sv[4], sla[2], sden[2], rden[2];
    __shared__ float ws[128];
    __shared__ int ssrc[64];
    if (j < 4) sv[j] = g_v2[j];
    if (j < 2) { sla[j] = g_la2[j]; sden[j] = 0.f; }
    __syncthreads();

    float aD0 = g_alD[d * 2], aD1 = g_alD[d * 2 + 1];
    float den0 = 0.f, den1 = 0.f;
    for (int pos = p0 + j; pos < p1; pos += 128) {
        int e = g_csr_e[pos];
        int s = g_csr_src[pos];
        float ale0, ale1;
        if (e < EE) {
            float e0 = ea[2 * e], e1 = ea[2 * e + 1];
            ale0 = e0 * sv[0] + e1 * sv[1];
            ale1 = e0 * sv[2] + e1 * sv[3];
        } else {
            ale0 = sla[0]; ale1 = sla[1];
        }
        float a0 = g_alS[s * 2 + 0] + aD0 + ale0;
        float a1 = g_alS[s * 2 + 1] + aD1 + ale1;
        a0 = a0 > 0.f ? a0 : 0.2f * a0;
        a1 = a1 > 0.f ? a1 : 0.2f * a1;
        float x0 = __expf(a0), x1 = __expf(a1);
        g_alpha[pos * 2 + 0] = x0; den0 += x0;
        g_alpha[pos * 2 + 1] = x1; den1 += x1;
    }
    for (int o = 16; o; o >>= 1) {
        den0 += __shfl_down_sync(0xFFFFFFFFu, den0, o);
        den1 += __shfl_down_sync(0xFFFFFFFFu, den1, o);
    }
    if ((j & 31) == 0) {
        atomicAdd(&sden[0], den0);
        atomicAdd(&sden[1], den1);
    }
    __syncthreads();
    if (j < 2) rden[j] = 1.f / sden[j];
    __syncthreads();

    float acc = 0.f;
    int hsel = j >> 6;
    for (int base = p0; base < p1; base += 64) {
        int m = min(64, p1 - base);
        if (j < m * 2) ws[j] = g_alpha[base * 2 + j] * rden[j & 1];
        if (j < m) ssrc[j] = g_csr_src[base + j];
        __syncthreads();
        for (int i = 0; i < m; i++)
            acc += g_A[(size_t)ssrc[i] * 128 + j] * ws[i * 2 + hsel];
        __syncthreads();
    }
    g_B[(size_t)NN * 128 + (size_t)d * 128 + j] = acc;
}

// ---------------- classifier (fused norm+ELU) --------------------------------
__global__ void k_cls(const float* __restrict__ Wc, const float* __restrict__ bc,
                      float* __restrict__ out) {
    __shared__ float wc[128 * 13];
    __shared__ float sbc[13];
    __shared__ float cs[128], cf[128];
    for (int i = threadIdx.x; i < 128 * 13; i += 256) wc[i] = Wc[i];
    if (threadIdx.x < 13) sbc[threadIdx.x] = bc[threadIdx.x];
    if (threadIdx.x < 128) { cs[threadIdx.x] = g_cscale[threadIdx.x]; cf[threadIdx.x] = g_cshift[threadIdx.x]; }
    __syncthreads();
    int warp = (blockIdx.x * 256 + threadIdx.x) >> 5;
    int lane = threadIdx.x & 31;
    int nw = (gridDim.x * 256) >> 5;
    const float* gat2 = g_B + (size_t)NN * 128;
    for (int n = warp; n < NN; n += nw) {
        float4 hv = *(const float4*)(gat2 + (size_t)n * 128 + lane * 4);
        int kb = lane * 4;
        float y0 = hv.x * cs[kb + 0] + cf[kb + 0]; y0 = y0 > 0.f ? y0 : expm1f(y0);
        float y1 = hv.y * cs[kb + 1] + cf[kb + 1]; y1 = y1 > 0.f ? y1 : expm1f(y1);
        float y2 = hv.z * cs[kb + 2] + cf[kb + 2]; y2 = y2 > 0.f ? y2 : expm1f(y2);
        float y3 = hv.w * cs[kb + 3] + cf[kb + 3]; y3 = y3 > 0.f ? y3 : expm1f(y3);
#pragma unroll
        for (int c = 0; c < 13; c++) {
            float p = y0 * wc[kb * 13 + c] + y1 * wc[(kb + 1) * 13 + c]
                    + y2 * wc[(kb + 2) * 13 + c] + y3 * wc[(kb + 3) * 13 + c];
            for (int o = 16; o; o >>= 1) p += __shfl_down_sync(0xFFFFFFFFu, p, o);
            if (lane == 0) out[n * 13 + c] = p + sbc[c];
        }
    }
}

// ---------------- launch ------------------------------------------------------
extern "C" void kernel_launch(void* const* d_in, const int* in_sizes, int n_in,
                              void* d_out, int out_size) {
    const float* x    = (const float*)d_in[0];
    const int*   ei   = (const int*)d_in[1];
    const float* ea   = (const float*)d_in[2];
    const float* W1   = (const float*)d_in[3];
    const float* We1  = (const float*)d_in[4];
    const float* as1  = (const float*)d_in[5];
    const float* ad1  = (const float*)d_in[6];
    const float* ae1  = (const float*)d_in[7];
    const float* b1   = (const float*)d_in[8];
    const float* gn1w = (const float*)d_in[9];
    const float* gn1b = (const float*)d_in[10];
    const float* gn1m = (const float*)d_in[11];
    const float* W2   = (const float*)d_in[12];
    const float* We2  = (const float*)d_in[13];
    const float* as2  = (const float*)d_in[14];
    const float* ad2  = (const float*)d_in[15];
    const float* ae2  = (const float*)d_in[16];
    const float* b2   = (const float*)d_in[17];
    const float* gn2w = (const float*)d_in[18];
    const float* gn2b = (const float*)d_in[19];
    const float* gn2m = (const float*)d_in[20];
    const float* Wc   = (const float*)d_in[21];
    const float* bc   = (const float*)d_in[22];
    float* out = (float*)d_out;

    float *pB, *pEam, *pCol;
    int* pCnt;
    cudaGetSymbolAddress((void**)&pB, g_B);
    cudaGetSymbolAddress((void**)&pEam, g_eamsum);
    cudaGetSymbolAddress((void**)&pCol, g_colstats);
    cudaGetSymbolAddress((void**)&pCnt, g_cnt);

    static int s_attr = 0;
    if (!s_attr) {
        cudaFuncSetAttribute(k_gemm2f, cudaFuncAttributeMaxDynamicSharedMemorySize, 256 * XPAD * 4);
        s_attr = 1;
    }

    int nb = (NN + 255) / 256;   // 196 scan blocks

    // ---- CSR build + precomputes ----
    k_zero2i<<<128, 256>>>(pCnt, NN, pEam, 2);
    k_cm<<<512, 256>>>(ei, ea);
    k_scan_block<<<nb, 256>>>();
    k_scan_part<<<1, 256>>>(nb);
    k_scan_add<<<nb, 256>>>();
    k_zeroi<<<128, 256>>>(pCnt, NN);
    k_fill<<<(ET + 255) / 256, 256>>>(ei);
    k_prep<<<1, 64>>>(We1, ae1, We2, ae2, W1, as1, ad1);
    k_prep2<<<4, 256>>>(W2, as2, ad2);

    // ---- layer 1 ----
    k_h1w<<<2048, 256>>>(x, W1);
    k_agg1<<<NN, 256>>>(ea);
    k_zero<<<2, 256>>>(pCol, 512);
    k_colsum2<<<(NN + 127) / 128, 256>>>(pB, 256, 128);
    k_stats<<<1, 256>>>(b1, gn1m, gn1w, gn1b, 256);

    // ---- layer 2 (fused norm + GEMM + logits) ----
    k_gemm2f<<<(NN + 63) / 64, 256, 256 * XPAD * 4>>>(W2);
    k_agg2<<<NN, 128>>>(ea);
    k_zero<<<2, 256>>>(pCol, 512);
    k_colsum2<<<(NN + 127) / 128, 128>>>(pB + (size_t)NN * 128, 128, 128);
    k_stats<<<1, 256>>>(b2, gn2m, gn2w, gn2b, 128);

    // ---- classifier (fused norm) ----
    k_cls<<<512, 256>>>(Wc, bc, out);
}

// round 4
// speedup vs baseline: 3.9878x; 1.5159x over previous
#include <cuda_runtime.h>
#include <cuda_bf16.h>
#include <math.h>

#define NN 50000
#define EE 400000
#define ET 450000   // EE + NN self loops
#define EPSN 1e-5f
#define XPAD 65

// ---------------- scratch (device globals) -----------------------------------
__device__ float g_A[(size_t)NN * 256];       // h1 (raw) -> h2
__device__ float g_B[(size_t)NN * 256];       // gat1 raw | [.. gat2 raw at +NN*128]
__device__ float g_alpha[(size_t)ET * 4];     // exp(alpha) in CSR order (layer2 stride 2)
__device__ float g_alS[(size_t)NN * 4];
__device__ float g_alD[(size_t)NN * 4];
__device__ float g_colstats[512];             // zero-initialized; k_stats re-zeroes after use
__device__ float g_cscale[256];
__device__ float g_cshift[256];
__device__ float g_eamsum[2];
__device__ float g_v1[8];
__device__ float g_v2[4];
__device__ float g_la1[4];
__device__ float g_la2[2];
__device__ float g_uS1[12], g_uD1[12];
__device__ float g_uS2[512], g_uD2[512];      // [k*2+h]
// CSR
__device__ int g_cnt[NN];
__device__ int g_rowptr[NN + 1];
__device__ int g_part[256];
__device__ int g_csr_src[ET];
__device__ int g_epos[ET];                    // edge -> CSR position

// f32x2 packed helpers
#define FMA2(acc, a, b) asm("fma.rn.f32x2 %0, %1, %2, %0;" : "+l"(acc) : "l"(a), "l"(b))
#define BCAST2(p, f)    asm("mov.b64 %0, {%1, %1};" : "=l"(p) : "f"(f))
#define PACK2(p, lo, hi) asm("mov.b64 %0, {%1, %2};" : "=l"(p) : "f"(lo), "f"(hi))
#define UNPK2(lo, hi, p) asm("mov.b64 {%0, %1}, %2;" : "=f"(lo), "=f"(hi) : "l"(p))

// ---------------- utility ----------------------------------------------------
__global__ void k_zero2i(int* p1, int n1, float* p2, int n2) {
    int i = blockIdx.x * blockDim.x + threadIdx.x;
    int st = gridDim.x * blockDim.x;
    for (int k = i; k < n1; k += st) p1[k] = 0;
    for (int k = i; k < n2; k += st) p2[k] = 0.f;
}

// ---------------- fused: dst-degree count + edge_attr mean -------------------
__global__ void k_cm(const int* __restrict__ ei, const float* __restrict__ ea) {
    float s0 = 0.f, s1 = 0.f;
    int st = gridDim.x * blockDim.x;
    for (int e = blockIdx.x * blockDim.x + threadIdx.x; e < ET; e += st) {
        int d = (e < EE) ? ei[EE + e] : (e - EE);
        atomicAdd(&g_cnt[d], 1);
        if (e < EE) { s0 += ea[2 * e]; s1 += ea[2 * e + 1]; }
    }
    for (int o = 16; o; o >>= 1) {
        s0 += __shfl_down_sync(0xFFFFFFFFu, s0, o);
        s1 += __shfl_down_sync(0xFFFFFFFFu, s1, o);
    }
    __shared__ float sh[16];
    int lane = threadIdx.x & 31, wid = threadIdx.x >> 5;
    if (lane == 0) { sh[wid] = s0; sh[8 + wid] = s1; }
    __syncthreads();
    if (threadIdx.x == 0) {
        float a = 0.f, b = 0.f;
        for (int w = 0; w < 8; w++) { a += sh[w]; b += sh[8 + w]; }
        atomicAdd(&g_eamsum[0], a);
        atomicAdd(&g_eamsum[1], b);
    }
}

// ---------------- small precomputes ------------------------------------------
__global__ void k_prep(const float* __restrict__ We1, const float* __restrict__ ae1,
                       const float* __restrict__ We2, const float* __restrict__ ae2,
                       const float* __restrict__ W1, const float* __restrict__ as1,
                       const float* __restrict__ ad1) {
    int t = threadIdx.x;
    if (t < 8) {
        int h = t >> 1, f = t & 1;
        float s = 0.f;
        for (int d = 0; d < 64; d++) s += We1[f * 256 + h * 64 + d] * ae1[h * 64 + d];
        g_v1[t] = s;
    } else if (t < 12) {
        int tt = t - 8, h = tt >> 1, f = tt & 1;
        float s = 0.f;
        for (int d = 0; d < 64; d++) s += We2[f * 128 + h * 64 + d] * ae2[h * 64 + d];
        g_v2[tt] = s;
    } else if (t < 24) {
        int idx = t - 12, f = idx >> 2, h = idx & 3;
        float s = 0.f;
        for (int d = 0; d < 64; d++) s += W1[f * 256 + h * 64 + d] * as1[h * 64 + d];
        g_uS1[idx] = s;
    } else if (t < 36) {
        int idx = t - 24, f = idx >> 2, h = idx & 3;
        float s = 0.f;
        for (int d = 0; d < 64; d++) s += W1[f * 256 + h * 64 + d] * ad1[h * 64 + d];
        g_uD1[idx] = s;
    }
    __syncthreads();
    if (t == 0) {
        float e0 = g_eamsum[0] / (float)EE;
        float e1 = g_eamsum[1] / (float)EE;
        for (int h = 0; h < 4; h++) g_la1[h] = e0 * g_v1[2 * h] + e1 * g_v1[2 * h + 1];
        for (int h = 0; h < 2; h++) g_la2[h] = e0 * g_v2[2 * h] + e1 * g_v2[2 * h + 1];
    }
}

// ---------------- CSR scan ---------------------------------------------------
__global__ void k_scan_block() {
    __shared__ int sh[256];
    int i = blockIdx.x * 256 + threadIdx.x;
    int v = (i < NN) ? g_cnt[i] : 0;
    sh[threadIdx.x] = v;
    __syncthreads();
    for (int o = 1; o < 256; o <<= 1) {
        int t = (threadIdx.x >= o) ? sh[threadIdx.x - o] : 0;
        __syncthreads();
        sh[threadIdx.x] += t;
        __syncthreads();
    }
    if (i < NN) g_rowptr[i] = sh[threadIdx.x] - v;
    if (threadIdx.x == 255) g_part[blockIdx.x] = sh[255];
}

__global__ void k_scan_part(int nb) {
    __shared__ int sh[256];
    int t = threadIdx.x;
    int v = (t < nb) ? g_part[t] : 0;
    sh[t] = v;
    __syncthreads();
    for (int o = 1; o < 256; o <<= 1) {
        int u = (t >= o) ? sh[t - o] : 0;
        __syncthreads();
        sh[t] += u;
        __syncthreads();
    }
    if (t < nb) g_part[t] = sh[t] - v;
}

// ---------------- layer1: h1 = x @ W1 + fused attention logits ---------------
__global__ void k_h1w(const float* __restrict__ x, const float* __restrict__ W1) {
    __shared__ float w[768];
    __shared__ float su[24];
    if (threadIdx.x < 256) {
        w[threadIdx.x] = W1[threadIdx.x];
        w[256 + threadIdx.x] = W1[256 + threadIdx.x];
        w[512 + threadIdx.x] = W1[512 + threadIdx.x];
    }
    if (threadIdx.x < 12) { su[threadIdx.x] = g_uS1[threadIdx.x]; su[12 + threadIdx.x] = g_uD1[threadIdx.x]; }
    __syncthreads();
    int i = blockIdx.x * blockDim.x + threadIdx.x;
    int st = gridDim.x * blockDim.x;
    for (; i < NN * 64; i += st) {
        int n = i >> 6, j4 = (i & 63) * 4;
        float x0 = __ldg(&x[3 * n]), x1 = __ldg(&x[3 * n + 1]), x2 = __ldg(&x[3 * n + 2]);
        float4 o;
        o.x = x0 * w[j4 + 0] + x1 * w[256 + j4 + 0] + x2 * w[512 + j4 + 0];
        o.y = x0 * w[j4 + 1] + x1 * w[256 + j4 + 1] + x2 * w[512 + j4 + 1];
        o.z = x0 * w[j4 + 2] + x1 * w[256 + j4 + 2] + x2 * w[512 + j4 + 2];
        o.w = x0 * w[j4 + 3] + x1 * w[256 + j4 + 3] + x2 * w[512 + j4 + 3];
        *(float4*)(g_A + (size_t)n * 256 + j4) = o;
        if ((i & 63) == 0) {
#pragma unroll
            for (int h = 0; h < 4; h++) {
                g_alS[n * 4 + h] = x0 * su[h] + x1 * su[4 + h] + x2 * su[8 + h];
                g_alD[n * 4 + h] = x0 * su[12 + h] + x1 * su[16 + h] + x2 * su[20 + h];
            }
        }
    }
}

// ---------------- scan finalize + cnt re-zero --------------------------------
__global__ void k_scan_addz() {
    int i = blockIdx.x * 256 + threadIdx.x;
    if (i < NN) { g_rowptr[i] += g_part[blockIdx.x]; g_cnt[i] = 0; }
    if (i == 0) g_rowptr[NN] = ET;
}

__global__ void k_fill(const int* __restrict__ ei) {
    int e = blockIdx.x * blockDim.x + threadIdx.x;
    if (e >= ET) return;
    int s, d;
    if (e < EE) { s = ei[e]; d = ei[EE + e]; } else { s = e - EE; d = s; }
    int pos = g_rowptr[d] + atomicAdd(&g_cnt[d], 1);
    g_csr_src[pos] = s;
    g_epos[e] = pos;
}

__global__ void k_prep2(const float* __restrict__ W2, const float* __restrict__ as2,
                        const float* __restrict__ ad2) {
    int t = blockIdx.x * blockDim.x + threadIdx.x;
    if (t >= 1024) return;
    int which = t >> 9;
    int kk = (t & 511) >> 1, h = t & 1;
    const float* a = which ? ad2 : as2;
    float s = 0.f;
    for (int d = 0; d < 64; d++) s += W2[kk * 128 + h * 64 + d] * a[h * 64 + d];
    if (which) g_uD2[kk * 2 + h] = s; else g_uS2[kk * 2 + h] = s;
}

// ---------------- edge-parallel alpha (exp), layer1 --------------------------
__global__ void k_alpha1(const int* __restrict__ ei, const float* __restrict__ ea) {
    int e = blockIdx.x * blockDim.x + threadIdx.x;
    if (e >= ET) return;
    int s, d;
    float ale0, ale1, ale2, ale3;
    if (e < EE) {
        s = ei[e]; d = ei[EE + e];
        float e0 = ea[2 * e], e1 = ea[2 * e + 1];
        ale0 = e0 * g_v1[0] + e1 * g_v1[1];
        ale1 = e0 * g_v1[2] + e1 * g_v1[3];
        ale2 = e0 * g_v1[4] + e1 * g_v1[5];
        ale3 = e0 * g_v1[6] + e1 * g_v1[7];
    } else {
        s = e - EE; d = s;
        ale0 = g_la1[0]; ale1 = g_la1[1]; ale2 = g_la1[2]; ale3 = g_la1[3];
    }
    float4 aS = *(const float4*)&g_alS[s * 4];
    float4 aD = *(const float4*)&g_alD[d * 4];
    float a0 = aS.x + aD.x + ale0;
    float a1 = aS.y + aD.y + ale1;
    float a2 = aS.z + aD.z + ale2;
    float a3 = aS.w + aD.w + ale3;
    a0 = a0 > 0.f ? a0 : 0.2f * a0;
    a1 = a1 > 0.f ? a1 : 0.2f * a1;
    a2 = a2 > 0.f ? a2 : 0.2f * a2;
    a3 = a3 > 0.f ? a3 : 0.2f * a3;
    float4 ex = make_float4(__expf(a0), __expf(a1), __expf(a2), __expf(a3));
    *(float4*)&g_alpha[(size_t)g_epos[e] * 4] = ex;
}

// ---------------- warp-per-(node,chunk) gather, layer1 -----------------------
__global__ void __launch_bounds__(256) k_gath1() {
    int gw = (blockIdx.x * 256 + threadIdx.x) >> 5;
    if (gw >= NN * 2) return;
    int d = gw >> 1;
    int lane = threadIdx.x & 31;
    int j = (gw & 1) * 128 + lane * 4;
    int h = j >> 6;
    int p0 = g_rowptr[d], p1 = g_rowptr[d + 1];
    float4 acc = make_float4(0.f, 0.f, 0.f, 0.f);
    float wsum = 0.f;
#pragma unroll 2
    for (int pos = p0; pos < p1; pos++) {
        int s = __ldg(&g_csr_src[pos]);
        float w = __ldg(&g_alpha[(size_t)pos * 4 + h]);
        float4 v = *(const float4*)(g_A + (size_t)s * 256 + j);
        wsum += w;
        acc.x += v.x * w; acc.y += v.y * w; acc.z += v.z * w; acc.w += v.w * w;
    }
    float r = 1.f / wsum;
    acc.x *= r; acc.y *= r; acc.z *= r; acc.w *= r;
    *(float4*)(g_B + (size_t)d * 256 + j) = acc;
}

// ---------------- GraphNorm stats --------------------------------------------
__global__ void k_colsum2(const float* __restrict__ X, int C, int rpb) {
    int j = threadIdx.x;
    int r0 = blockIdx.x * rpb, r1 = min(r0 + rpb, NN);
    float s = 0.f, q = 0.f;
    for (int r = r0; r < r1; r++) {
        float v = X[(size_t)r * C + j];
        s += v;
        q += v * v;
    }
    atomicAdd(&g_colstats[j], s);
    atomicAdd(&g_colstats[256 + j], q);
}

// computes cscale/cshift, then re-zeroes colstats for the next user
__global__ void k_stats(const float* __restrict__ b, const float* __restrict__ ms,
                        const float* __restrict__ w, const float* __restrict__ gb, int C) {
    int j = threadIdx.x;
    if (j < C) {
        float invN = 1.0f / NN;
        float sum = g_colstats[j], sq = g_colstats[256 + j];
        float m = sum * invN + b[j];
        float cp = b[j] - m * ms[j];
        float var = sq * invN + 2.f * cp * (sum * invN) + cp * cp;
        float rstd = rsqrtf(var + EPSN);
        g_cscale[j] = w[j] * rstd;
        g_cshift[j] = cp * w[j] * rstd + gb[j];
    }
    g_colstats[j] = 0.f;
    g_colstats[256 + j] = 0.f;
}

// ---------------- fused GEMM2: norm+ELU on load, f32x2 FMA, logits epilogue --
__global__ void __launch_bounds__(256) k_gemm2f(const float* __restrict__ W2) {
    extern __shared__ float xs[];          // [256][XPAD] k-major
    __shared__ float cs[256], cf[256], us[512], ud[512];
    int tid = threadIdx.x;
    cs[tid] = g_cscale[tid];
    cf[tid] = g_cshift[tid];
    us[tid] = g_uS2[tid]; us[256 + tid] = g_uS2[256 + tid];
    ud[tid] = g_uD2[tid]; ud[256 + tid] = g_uD2[256 + tid];
    __syncthreads();

    int r0 = blockIdx.x * 64;
    for (int idx = tid; idx < 64 * 64; idx += 256) {
        int r = idx >> 6;
        int kq = idx & 63;
        int row = r0 + r;
        float4 v = make_float4(0.f, 0.f, 0.f, 0.f);
        if (row < NN) v = *(const float4*)(g_B + (size_t)row * 256 + kq * 4);
        int k4 = kq * 4;
        float y0 = v.x * cs[k4 + 0] + cf[k4 + 0]; y0 = y0 > 0.f ? y0 : expm1f(y0);
        float y1 = v.y * cs[k4 + 1] + cf[k4 + 1]; y1 = y1 > 0.f ? y1 : expm1f(y1);
        float y2 = v.z * cs[k4 + 2] + cf[k4 + 2]; y2 = y2 > 0.f ? y2 : expm1f(y2);
        float y3 = v.w * cs[k4 + 3] + cf[k4 + 3]; y3 = y3 > 0.f ? y3 : expm1f(y3);
        xs[(k4 + 0) * XPAD + r] = y0;
        xs[(k4 + 1) * XPAD + r] = y1;
        xs[(k4 + 2) * XPAD + r] = y2;
        xs[(k4 + 3) * XPAD + r] = y3;
    }
    __syncthreads();

    int tx = tid & 31, ty = tid >> 5;
    int c0 = tx * 4, rb = ty * 8;
    unsigned long long acc[4][4];
#pragma unroll
    for (int p = 0; p < 4; p++)
#pragma unroll
        for (int c = 0; c < 4; c++) acc[p][c] = 0ull;

    const float* W2p = W2 + c0;
#pragma unroll 4
    for (int k = 0; k < 256; k++) {
        const float* xr = xs + k * XPAD + rb;
        float4 w = __ldg((const float4*)(W2p + k * 128));
        unsigned long long xp0, xp1, xp2, xp3;
        PACK2(xp0, xr[0], xr[1]);
        PACK2(xp1, xr[2], xr[3]);
        PACK2(xp2, xr[4], xr[5]);
        PACK2(xp3, xr[6], xr[7]);
        unsigned long long wp;
        BCAST2(wp, w.x);
        FMA2(acc[0][0], xp0, wp); FMA2(acc[1][0], xp1, wp); FMA2(acc[2][0], xp2, wp); FMA2(acc[3][0], xp3, wp);
        BCAST2(wp, w.y);
        FMA2(acc[0][1], xp0, wp); FMA2(acc[1][1], xp1, wp); FMA2(acc[2][1], xp2, wp); FMA2(acc[3][1], xp3, wp);
        BCAST2(wp, w.z);
        FMA2(acc[0][2], xp0, wp); FMA2(acc[1][2], xp1, wp); FMA2(acc[2][2], xp2, wp); FMA2(acc[3][2], xp3, wp);
        BCAST2(wp, w.w);
        FMA2(acc[0][3], xp0, wp); FMA2(acc[1][3], xp1, wp); FMA2(acc[2][3], xp2, wp); FMA2(acc[3][3], xp3, wp);
    }

#pragma unroll
    for (int p = 0; p < 4; p++) {
        int row = r0 + rb + 2 * p;
        float l0, h0, l1, h1, l2, h2v, l3, h3;
        UNPK2(l0, h0, acc[p][0]);
        UNPK2(l1, h1, acc[p][1]);
        UNPK2(l2, h2v, acc[p][2]);
        UNPK2(l3, h3, acc[p][3]);
        if (row < NN)     *(float4*)(g_A + (size_t)row * 128 + c0)       = make_float4(l0, l1, l2, l3);
        if (row + 1 < NN) *(float4*)(g_A + (size_t)(row + 1) * 128 + c0) = make_float4(h0, h1, h2v, h3);
    }

    {
        int row = tid >> 2, q = tid & 3;
        int grow = r0 + row;
        const float* uu = (q < 2) ? (us + q) : (ud + (q - 2));
        float s = 0.f;
#pragma unroll 8
        for (int k = 0; k < 256; k++)
            s += xs[k * XPAD + row] * uu[k * 2];
        if (grow < NN) {
            if (q < 2) g_alS[grow * 2 + q] = s;
            else       g_alD[grow * 2 + (q - 2)] = s;
        }
    }
}

// ---------------- edge-parallel alpha, layer2 --------------------------------
__global__ void k_alpha2(const int* __restrict__ ei, const float* __restrict__ ea) {
    int e = blockIdx.x * blockDim.x + threadIdx.x;
    if (e >= ET) return;
    int s, d;
    float ale0, ale1;
    if (e < EE) {
        s = ei[e]; d = ei[EE + e];
        float e0 = ea[2 * e], e1 = ea[2 * e + 1];
        ale0 = e0 * g_v2[0] + e1 * g_v2[1];
        ale1 = e0 * g_v2[2] + e1 * g_v2[3];
    } else {
        s = e - EE; d = s;
        ale0 = g_la2[0]; ale1 = g_la2[1];
    }
    float2 aS = *(const float2*)&g_alS[s * 2];
    float2 aD = *(const float2*)&g_alD[d * 2];
    float a0 = aS.x + aD.x + ale0;
    float a1 = aS.y + aD.y + ale1;
    a0 = a0 > 0.f ? a0 : 0.2f * a0;
    a1 = a1 > 0.f ? a1 : 0.2f * a1;
    float2 ex = make_float2(__expf(a0), __expf(a1));
    *(float2*)&g_alpha[(size_t)g_epos[e] * 2] = ex;
}

// ---------------- warp-per-node gather, layer2 -------------------------------
__global__ void __launch_bounds__(256) k_gath2() {
    int d = (blockIdx.x * 256 + threadIdx.x) >> 5;
    if (d >= NN) return;
    int lane = threadIdx.x & 31;
    int j = lane * 4;
    int h = j >> 6;
    int p0 = g_rowptr[d], p1 = g_rowptr[d + 1];
    float4 acc = make_float4(0.f, 0.f, 0.f, 0.f);
    float wsum = 0.f;
#pragma unroll 2
    for (int pos = p0; pos < p1; pos++) {
        int s = __ldg(&g_csr_src[pos]);
        float w = __ldg(&g_alpha[(size_t)pos * 2 + h]);
        float4 v = *(const float4*)(g_A + (size_t)s * 128 + j);
        wsum += w;
        acc.x += v.x * w; acc.y += v.y * w; acc.z += v.z * w; acc.w += v.w * w;
    }
    float r = 1.f / wsum;
    acc.x *= r; acc.y *= r; acc.z *= r; acc.w *= r;
    *(float4*)(g_B + (size_t)NN * 128 + (size_t)d * 128 + j) = acc;
}

// ---------------- classifier (fused norm+ELU) --------------------------------
__global__ void k_cls(const float* __restrict__ Wc, const float* __restrict__ bc,
                      float* __restrict__ out) {
    __shared__ float wc[128 * 13];
    __shared__ float sbc[13];
    __shared__ float cs[128], cf[128];
    for (int i = threadIdx.x; i < 128 * 13; i += 256) wc[i] = Wc[i];
    if (threadIdx.x < 13) sbc[threadIdx.x] = bc[threadIdx.x];
    if (threadIdx.x < 128) { cs[threadIdx.x] = g_cscale[threadIdx.x]; cf[threadIdx.x] = g_cshift[threadIdx.x]; }
    __syncthreads();
    int warp = (blockIdx.x * 256 + threadIdx.x) >> 5;
    int lane = threadIdx.x & 31;
    int nw = (gridDim.x * 256) >> 5;
    const float* gat2 = g_B + (size_t)NN * 128;
    for (int n = warp; n < NN; n += nw) {
        float4 hv = *(const float4*)(gat2 + (size_t)n * 128 + lane * 4);
        int kb = lane * 4;
        float y0 = hv.x * cs[kb + 0] + cf[kb + 0]; y0 = y0 > 0.f ? y0 : expm1f(y0);
        float y1 = hv.y * cs[kb + 1] + cf[kb + 1]; y1 = y1 > 0.f ? y1 : expm1f(y1);
        float y2 = hv.z * cs[kb + 2] + cf[kb + 2]; y2 = y2 > 0.f ? y2 : expm1f(y2);
        float y3 = hv.w * cs[kb + 3] + cf[kb + 3]; y3 = y3 > 0.f ? y3 : expm1f(y3);
#pragma unroll
        for (int c = 0; c < 13; c++) {
            float p = y0 * wc[kb * 13 + c] + y1 * wc[(kb + 1) * 13 + c]
                    + y2 * wc[(kb + 2) * 13 + c] + y3 * wc[(kb + 3) * 13 + c];
            for (int o = 16; o; o >>= 1) p += __shfl_down_sync(0xFFFFFFFFu, p, o);
            if (lane == 0) out[n * 13 + c] = p + sbc[c];
        }
    }
}

// ---------------- launch ------------------------------------------------------
extern "C" void kernel_launch(void* const* d_in, const int* in_sizes, int n_in,
                              void* d_out, int out_size) {
    const float* x    = (const float*)d_in[0];
    const int*   ei   = (const int*)d_in[1];
    const float* ea   = (const float*)d_in[2];
    const float* W1   = (const float*)d_in[3];
    const float* We1  = (const float*)d_in[4];
    const float* as1  = (const float*)d_in[5];
    const float* ad1  = (const float*)d_in[6];
    const float* ae1  = (const float*)d_in[7];
    const float* b1   = (const float*)d_in[8];
    const float* gn1w = (const float*)d_in[9];
    const float* gn1b = (const float*)d_in[10];
    const float* gn1m = (const float*)d_in[11];
    const float* W2   = (const float*)d_in[12];
    const float* We2  = (const float*)d_in[13];
    const float* as2  = (const float*)d_in[14];
    const float* ad2  = (const float*)d_in[15];
    const float* ae2  = (const float*)d_in[16];
    const float* b2   = (const float*)d_in[17];
    const float* gn2w = (const float*)d_in[18];
    const float* gn2b = (const float*)d_in[19];
    const float* gn2m = (const float*)d_in[20];
    const float* Wc   = (const float*)d_in[21];
    const float* bc   = (const float*)d_in[22];
    float* out = (float*)d_out;

    float *pB, *pEam;
    int* pCnt;
    cudaGetSymbolAddress((void**)&pB, g_B);
    cudaGetSymbolAddress((void**)&pEam, g_eamsum);
    cudaGetSymbolAddress((void**)&pCnt, g_cnt);

    cudaFuncSetAttribute(k_gemm2f, cudaFuncAttributeMaxDynamicSharedMemorySize, 256 * XPAD * 4);

    int nb = (NN + 255) / 256;   // 196 scan blocks

    // ---- CSR build + precomputes (ordered so k_h1w sits at profile idx 5) ----
    k_zero2i<<<128, 256>>>(pCnt, NN, pEam, 2);          // 0
    k_cm<<<512, 256>>>(ei, ea);                         // 1
    k_prep<<<1, 64>>>(We1, ae1, We2, ae2, W1, as1, ad1);// 2
    k_scan_block<<<nb, 256>>>();                        // 3
    k_scan_part<<<1, 256>>>(nb);                        // 4
    k_h1w<<<2048, 256>>>(x, W1);                        // 5  <- profiled
    k_scan_addz<<<nb, 256>>>();                         // 6
    k_fill<<<(ET + 255) / 256, 256>>>(ei);              // 7
    k_prep2<<<4, 256>>>(W2, as2, ad2);                  // 8

    // ---- layer 1 ----
    k_alpha1<<<(ET + 255) / 256, 256>>>(ei, ea);        // 9
    k_gath1<<<(NN * 2 * 32 + 255) / 256, 256>>>();      // 10
    k_colsum2<<<(NN + 127) / 128, 256>>>(pB, 256, 128); // 11
    k_stats<<<1, 256>>>(b1, gn1m, gn1w, gn1b, 256);     // 12

    // ---- layer 2 ----
    k_gemm2f<<<(NN + 63) / 64, 256, 256 * XPAD * 4>>>(W2); // 13
    k_alpha2<<<(ET + 255) / 256, 256>>>(ei, ea);           // 14
    k_gath2<<<(NN * 32 + 255) / 256, 256>>>();             // 15
    k_colsum2<<<(NN + 127) / 128, 128>>>(pB + (size_t)NN * 128, 128, 128); // 16
    k_stats<<<1, 256>>>(b2, gn2m, gn2w, gn2b, 128);        // 17

    // ---- classifier ----
    k_cls<<<512, 256>>>(Wc, bc, out);                      // 18
}